// round 8
// baseline (speedup 1.0000x reference)
#include <cuda_runtime.h>
#include <cstdint>
#include <math.h>

#define NROWS 4096
#define DDIM  1024
#define DELTA 0.2f
#define QS    127.0f                 // int8 quant scale
#define INV_SS (1.0f / 16129.0f)     // 1/127^2

#define TILE_M 128
#define TILE_N 128
#define KC     128                   // K elems per chunk (s8 -> 128 B/row)
#define NCHUNK (DDIM / KC)           // 8
#define STAGES 3

#define GRID_M (NROWS / TILE_M)      // 32
#define GRID_N (NROWS / TILE_N)      // 32
#define NUM_TILES (GRID_M * GRID_N)  // 1024

#define A_BYTES     (TILE_M * 128)
#define B_BYTES     (TILE_N * 128)
#define STAGE_BYTES (A_BYTES + B_BYTES)
#define SMEM_TOTAL  (STAGES * STAGE_BYTES)  // 98304 -> 2 CTAs/SM

// Scratch (allocation-free contract). s8 data stored as packed u32 words.
__device__ uint32_t g_X8[NROWS * DDIM / 4];
__device__ uint32_t g_Y8[NROWS * DDIM / 4];
__device__ float g_pos[NROWS];
__device__ float g_partials[NUM_TILES];
__device__ unsigned g_ticket = 0;

// ---------------------------------------------------------------------------
// helpers
// ---------------------------------------------------------------------------
__device__ __forceinline__ uint32_t smem_u32(const void* p) {
    uint32_t a;
    asm("{ .reg .u64 t; cvta.to.shared.u64 t, %1; cvt.u32.u64 %0, t; }" : "=r"(a) : "l"(p));
    return a;
}
#define SW128(o) ((o) ^ (((o) >> 3) & 0x70))

#define CP_ASYNC_16(dst_u32, src_ptr) \
    asm volatile("cp.async.cg.shared.global [%0], [%1], 16;" :: "r"(dst_u32), "l"(src_ptr))
#define CP_ASYNC_COMMIT() asm volatile("cp.async.commit_group;" ::: "memory")
#define CP_ASYNC_WAIT_1() asm volatile("cp.async.wait_group 1;" ::: "memory")

__device__ __forceinline__ void ldsm_x4(uint32_t* r, uint32_t addr) {
    asm volatile("ldmatrix.sync.aligned.m8n8.x4.shared.b16 {%0,%1,%2,%3}, [%4];"
                 : "=r"(r[0]), "=r"(r[1]), "=r"(r[2]), "=r"(r[3]) : "r"(addr));
}
// INT8 MMA: m16n8k32, s32 accum. Fragment byte layout identical to e4m3 k32.
__device__ __forceinline__ void mma_s8(int* c, const uint32_t* a, const uint32_t* b) {
    asm volatile(
        "mma.sync.aligned.m16n8k32.row.col.s32.s8.s8.s32 "
        "{%0,%1,%2,%3}, {%4,%5,%6,%7}, {%8,%9}, {%0,%1,%2,%3};"
        : "+r"(c[0]), "+r"(c[1]), "+r"(c[2]), "+r"(c[3])
        : "r"(a[0]), "r"(a[1]), "r"(a[2]), "r"(a[3]), "r"(b[0]), "r"(b[1]));
}
// pack 4 floats -> 4 s8 bytes (byte0 = x0). |x| << 127 so no saturation risk.
__device__ __forceinline__ uint32_t pack_s8x4(float x0, float x1, float x2, float x3) {
    int v0 = __float2int_rn(x0), v1 = __float2int_rn(x1);
    int v2 = __float2int_rn(x2), v3 = __float2int_rn(x3);
    return (uint32_t)(v0 & 0xFF) | ((uint32_t)(v1 & 0xFF) << 8) |
           ((uint32_t)(v2 & 0xFF) << 16) | ((uint32_t)v3 << 24);
}

// ---------------------------------------------------------------------------
// Kernel 1: warp-per-row normalize (fp32 -> s8 * 127) + exact fp32 pos.
// ---------------------------------------------------------------------------
__global__ void __launch_bounds__(256) normalize_kernel(const float* __restrict__ X,
                                                        const float* __restrict__ Y) {
    const int wid  = threadIdx.x >> 5;
    const int lane = threadIdx.x & 31;
    const int row  = blockIdx.x * 8 + wid;

    const float4* xr = reinterpret_cast<const float4*>(X + (size_t)row * DDIM);
    const float4* yr = reinterpret_cast<const float4*>(Y + (size_t)row * DDIM);

    float4 xv[8], yv[8];
    #pragma unroll
    for (int i = 0; i < 8; i++) { xv[i] = xr[lane + 32 * i]; yv[i] = yr[lane + 32 * i]; }

    float ssx = 0.f, ssy = 0.f, sxy = 0.f;
    #pragma unroll
    for (int i = 0; i < 8; i++) {
        ssx += xv[i].x * xv[i].x + xv[i].y * xv[i].y + xv[i].z * xv[i].z + xv[i].w * xv[i].w;
        ssy += yv[i].x * yv[i].x + yv[i].y * yv[i].y + yv[i].z * yv[i].z + yv[i].w * yv[i].w;
        sxy += xv[i].x * yv[i].x + xv[i].y * yv[i].y + xv[i].z * yv[i].z + xv[i].w * yv[i].w;
    }
    #pragma unroll
    for (int off = 16; off > 0; off >>= 1) {
        ssx += __shfl_xor_sync(0xFFFFFFFFu, ssx, off);
        ssy += __shfl_xor_sync(0xFFFFFFFFu, ssy, off);
        sxy += __shfl_xor_sync(0xFFFFFFFFu, sxy, off);
    }
    const float nx = fmaxf(sqrtf(ssx), 1e-8f);
    const float ny = fmaxf(sqrtf(ssy), 1e-8f);
    const float sx = QS / nx;
    const float sy = QS / ny;
    if (lane == 0) g_pos[row] = sxy / (nx * ny);

    uint32_t* dx = g_X8 + (size_t)row * (DDIM / 4);
    uint32_t* dy = g_Y8 + (size_t)row * (DDIM / 4);
    #pragma unroll
    for (int i = 0; i < 8; i++) {
        dx[lane + 32 * i] = pack_s8x4(xv[i].x * sx, xv[i].y * sx, xv[i].z * sx, xv[i].w * sx);
        dy[lane + 32 * i] = pack_s8x4(yv[i].x * sy, yv[i].y * sy, yv[i].z * sy, yv[i].w * sy);
    }
}

// ---------------------------------------------------------------------------
// Kernel 2: s8 IMMA GEMM, 128x128 tile, 2 CTAs/SM, fused hinge epilogue
// + deterministic last-CTA final reduction.
// 8 warps in 2(m) x 4(n); warp tile 64x32 => acc[4][4][4] (s32).
// ---------------------------------------------------------------------------
__global__ void __launch_bounds__(256, 2) gemm_hinge_kernel(float* __restrict__ out) {
    extern __shared__ char smem[];
    const uint32_t sb = smem_u32(smem);
    const int tid  = threadIdx.x;
    const int wid  = tid >> 5;
    const int lane = tid & 31;
    const int warp_m = wid & 1;
    const int warp_n = wid >> 1;
    const int bm = blockIdx.y * TILE_M;
    const int bn = blockIdx.x * TILE_N;

    int acc[4][4][4];
    #pragma unroll
    for (int i = 0; i < 4; i++)
        #pragma unroll
        for (int j = 0; j < 4; j++)
            #pragma unroll
            for (int e = 0; e < 4; e++) acc[i][j][e] = 0;

    // loaders: 128-B rows of s8; each chunk is 128 s8 columns
    const int ld_row = tid >> 3;          // 0..31
    const int ld_c   = tid & 7;           // 16-B column
    auto load_chunk = [&](int j, int s) {
        const uint32_t stage = sb + s * STAGE_BYTES;
        const int k0w = j * (KC / 4);     // u32-word offset of chunk
        #pragma unroll
        for (int q = 0; q < 4; q++) {     // A: 128 rows
            int row = ld_row + q * 32;
            const uint32_t* src = g_X8 + (size_t)(bm + row) * (DDIM / 4) + k0w + ld_c * 4;
            uint32_t off = (uint32_t)(row * 128 + ld_c * 16);
            CP_ASYNC_16(stage + SW128(off), src);
        }
        #pragma unroll
        for (int q = 0; q < 4; q++) {     // B: 128 rows
            int row = ld_row + q * 32;
            const uint32_t* src = g_Y8 + (size_t)(bn + row) * (DDIM / 4) + k0w + ld_c * 4;
            uint32_t off = (uint32_t)(row * 128 + ld_c * 16);
            CP_ASYNC_16(stage + A_BYTES + SW128(off), src);
        }
    };

    #pragma unroll
    for (int j = 0; j < STAGES - 1; j++) {
        load_chunk(j, j);
        CP_ASYNC_COMMIT();
    }

    // ldmatrix per-lane components (kstep = 32 bytes)
    const int a_row_l = (lane & 15);
    const int a_kb_l  = (lane >> 4) << 4;
    const int b_row_l = (lane & 7) + ((lane >> 4) << 3);
    const int b_kb_l  = ((lane >> 3) & 1) << 4;

    int s = 0;
    for (int j = 0; j < NCHUNK; j++) {
        CP_ASYNC_WAIT_1();
        __syncthreads();
        if (j + STAGES - 1 < NCHUNK) {
            int s2 = s + STAGES - 1; if (s2 >= STAGES) s2 -= STAGES;
            load_chunk(j + STAGES - 1, s2);
        }
        CP_ASYNC_COMMIT();

        const uint32_t Abase = sb + s * STAGE_BYTES;
        const uint32_t Bbase = Abase + A_BYTES;

        #pragma unroll
        for (int kk = 0; kk < 4; kk++) {          // 4 ksteps x 32 s8 = 128
            const int kb = kk * 32;
            uint32_t afr[4][4];
            #pragma unroll
            for (int im = 0; im < 4; im++) {
                int row = warp_m * 64 + im * 16 + a_row_l;
                ldsm_x4(afr[im], Abase + SW128((uint32_t)(row * 128 + kb + a_kb_l)));
            }
            uint32_t bfr[2][4];
            #pragma unroll
            for (int jb = 0; jb < 2; jb++) {
                int row = warp_n * 32 + jb * 16 + b_row_l;
                ldsm_x4(bfr[jb], Bbase + SW128((uint32_t)(row * 128 + kb + b_kb_l)));
            }
            #pragma unroll
            for (int im = 0; im < 4; im++) {
                #pragma unroll
                for (int jb = 0; jb < 2; jb++) {
                    mma_s8(acc[im][2 * jb],     afr[im], &bfr[jb][0]);
                    mma_s8(acc[im][2 * jb + 1], afr[im], &bfr[jb][2]);
                }
            }
        }
        s++; if (s >= STAGES) s = 0;
    }

    // Fused epilogue: acc holds 127^2*S (exact s32). hinge = max(0, (D-pos) + acc/127^2)
    float psum = 0.f;
    #pragma unroll
    for (int im = 0; im < 4; im++) {
        const int r0 = bm + warp_m * 64 + im * 16 + (lane >> 2);
        const int r1 = r0 + 8;
        const float d0 = DELTA - __ldg(&g_pos[r0]);
        const float d1 = DELTA - __ldg(&g_pos[r1]);
        #pragma unroll
        for (int t = 0; t < 4; t++) {
            const int c0 = bn + warp_n * 32 + t * 8 + (lane & 3) * 2;
            const int c1 = c0 + 1;
            float h;
            h = fmaxf(0.f, fmaf((float)acc[im][t][0], INV_SS, d0)); psum += (r0 != c0) ? h : 0.f;
            h = fmaxf(0.f, fmaf((float)acc[im][t][1], INV_SS, d0)); psum += (r0 != c1) ? h : 0.f;
            h = fmaxf(0.f, fmaf((float)acc[im][t][2], INV_SS, d1)); psum += (r1 != c0) ? h : 0.f;
            h = fmaxf(0.f, fmaf((float)acc[im][t][3], INV_SS, d1)); psum += (r1 != c1) ? h : 0.f;
        }
    }

    #pragma unroll
    for (int off = 16; off > 0; off >>= 1)
        psum += __shfl_down_sync(0xFFFFFFFFu, psum, off);
    __shared__ float warp_sums[8];
    __shared__ bool s_last;
    if (lane == 0) warp_sums[wid] = psum;
    __syncthreads();
    if (tid == 0) {
        float tot = 0.f;
        #pragma unroll
        for (int w = 0; w < 8; w++) tot += warp_sums[w];
        g_partials[blockIdx.y * GRID_N + blockIdx.x] = tot;
        __threadfence();
        unsigned t = atomicAdd(&g_ticket, 1u);
        s_last = (t == NUM_TILES - 1);
    }
    __syncthreads();

    if (s_last) {
        float sloc = 0.f;
        #pragma unroll
        for (int i = 0; i < NUM_TILES / 256; i++)
            sloc += __ldcg(&g_partials[tid + i * 256]);
        #pragma unroll
        for (int off = 16; off > 0; off >>= 1)
            sloc += __shfl_down_sync(0xFFFFFFFFu, sloc, off);
        if (lane == 0) warp_sums[wid] = sloc;
        __syncthreads();
        if (tid == 0) {
            float tot = 0.f;
            #pragma unroll
            for (int w = 0; w < 8; w++) tot += warp_sums[w];
            out[0] = tot;
            g_ticket = 0;   // reset for next graph replay
        }
    }
}

extern "C" void kernel_launch(void* const* d_in, const int* in_sizes, int n_in,
                              void* d_out, int out_size) {
    const float* X = (const float*)d_in[0];
    const float* Y = (const float*)d_in[1];
    float* out = (float*)d_out;

    cudaFuncSetAttribute(gemm_hinge_kernel,
                         cudaFuncAttributeMaxDynamicSharedMemorySize, SMEM_TOTAL);

    normalize_kernel<<<NROWS / 8, 256>>>(X, Y);
    dim3 grid(GRID_N, GRID_M);
    gemm_hinge_kernel<<<grid, 256, SMEM_TOTAL>>>(out);
}

// round 9
// speedup vs baseline: 2.2376x; 2.2376x over previous
#include <cuda_runtime.h>
#include <cuda_fp16.h>
#include <cstdint>
#include <math.h>

#define NROWS 4096
#define DDIM  1024
#define DELTA 0.2f
#define QSCALE 16.0f               // per-operand quant scale; S is scaled by 256
#define INV_SS (1.0f / 256.0f)

#define TILE_M 128
#define TILE_N 128
#define KC     128                  // K elems per chunk (fp8 -> 128 B/row)
#define NCHUNK (DDIM / KC)          // 8
#define STAGES 3

#define GRID_M (NROWS / TILE_M)     // 32
#define GRID_N (NROWS / TILE_N)     // 32
#define NUM_TILES (GRID_M * GRID_N) // 1024

#define A_BYTES     (TILE_M * 128)
#define B_BYTES     (TILE_N * 128)
#define STAGE_BYTES (A_BYTES + B_BYTES)
#define SMEM_TOTAL  (STAGES * STAGE_BYTES)  // 98304 -> 2 CTAs/SM

// Scratch (allocation-free contract). fp8 data stored as packed u32 words.
__device__ uint32_t g_X8[NROWS * DDIM / 4];
__device__ uint32_t g_Y8[NROWS * DDIM / 4];
__device__ float g_pos[NROWS];
__device__ float g_partials[NUM_TILES];
__device__ unsigned g_ticket = 0;

// ---------------------------------------------------------------------------
// helpers
// ---------------------------------------------------------------------------
__device__ __forceinline__ uint32_t smem_u32(const void* p) {
    uint32_t a;
    asm("{ .reg .u64 t; cvta.to.shared.u64 t, %1; cvt.u32.u64 %0, t; }" : "=r"(a) : "l"(p));
    return a;
}
#define SW128(o) ((o) ^ (((o) >> 3) & 0x70))

#define CP_ASYNC_16(dst_u32, src_ptr) \
    asm volatile("cp.async.cg.shared.global [%0], [%1], 16;" :: "r"(dst_u32), "l"(src_ptr))
#define CP_ASYNC_COMMIT() asm volatile("cp.async.commit_group;" ::: "memory")
#define CP_ASYNC_WAIT_1() asm volatile("cp.async.wait_group 1;" ::: "memory")

__device__ __forceinline__ void ldsm_x4(uint32_t* r, uint32_t addr) {
    asm volatile("ldmatrix.sync.aligned.m8n8.x4.shared.b16 {%0,%1,%2,%3}, [%4];"
                 : "=r"(r[0]), "=r"(r[1]), "=r"(r[2]), "=r"(r[3]) : "r"(addr));
}
// FP8 e4m3 MMA with FP16 accumulators: m16n8k32. d/c are 2 x f16x2 regs:
// reg0 = (row lane>>2,  cols 2*(lane&3), +1), reg1 = same cols at row +8.
__device__ __forceinline__ void mma_fp8_h(uint32_t* c, const uint32_t* a, const uint32_t* b) {
    asm volatile(
        "mma.sync.aligned.m16n8k32.row.col.f16.e4m3.e4m3.f16 "
        "{%0,%1}, {%2,%3,%4,%5}, {%6,%7}, {%0,%1};"
        : "+r"(c[0]), "+r"(c[1])
        : "r"(a[0]), "r"(a[1]), "r"(a[2]), "r"(a[3]), "r"(b[0]), "r"(b[1]));
}
// pack 4 floats -> 4 e4m3 bytes (byte0 = x0). cvt e4m3x2 dest must be .b16.
__device__ __forceinline__ uint32_t pack_e4m3x4(float x0, float x1, float x2, float x3) {
    uint16_t lo, hi;
    asm("cvt.rn.satfinite.e4m3x2.f32 %0, %1, %2;" : "=h"(lo) : "f"(x1), "f"(x0));
    asm("cvt.rn.satfinite.e4m3x2.f32 %0, %1, %2;" : "=h"(hi) : "f"(x3), "f"(x2));
    return (uint32_t)lo | ((uint32_t)hi << 16);
}

// ---------------------------------------------------------------------------
// Kernel 1: warp-per-row normalize (fp32 -> e4m3 * QSCALE) + exact fp32 pos.
// ---------------------------------------------------------------------------
__global__ void __launch_bounds__(256) normalize_kernel(const float* __restrict__ X,
                                                        const float* __restrict__ Y) {
    const int wid  = threadIdx.x >> 5;
    const int lane = threadIdx.x & 31;
    const int row  = blockIdx.x * 8 + wid;

    const float4* xr = reinterpret_cast<const float4*>(X + (size_t)row * DDIM);
    const float4* yr = reinterpret_cast<const float4*>(Y + (size_t)row * DDIM);

    float4 xv[8], yv[8];
    #pragma unroll
    for (int i = 0; i < 8; i++) { xv[i] = xr[lane + 32 * i]; yv[i] = yr[lane + 32 * i]; }

    float ssx = 0.f, ssy = 0.f, sxy = 0.f;
    #pragma unroll
    for (int i = 0; i < 8; i++) {
        ssx += xv[i].x * xv[i].x + xv[i].y * xv[i].y + xv[i].z * xv[i].z + xv[i].w * xv[i].w;
        ssy += yv[i].x * yv[i].x + yv[i].y * yv[i].y + yv[i].z * yv[i].z + yv[i].w * yv[i].w;
        sxy += xv[i].x * yv[i].x + xv[i].y * yv[i].y + xv[i].z * yv[i].z + xv[i].w * yv[i].w;
    }
    #pragma unroll
    for (int off = 16; off > 0; off >>= 1) {
        ssx += __shfl_xor_sync(0xFFFFFFFFu, ssx, off);
        ssy += __shfl_xor_sync(0xFFFFFFFFu, ssy, off);
        sxy += __shfl_xor_sync(0xFFFFFFFFu, sxy, off);
    }
    const float nx = fmaxf(sqrtf(ssx), 1e-8f);
    const float ny = fmaxf(sqrtf(ssy), 1e-8f);
    const float sx = QSCALE / nx;
    const float sy = QSCALE / ny;
    if (lane == 0) g_pos[row] = sxy / (nx * ny);

    uint32_t* dx = g_X8 + (size_t)row * (DDIM / 4);
    uint32_t* dy = g_Y8 + (size_t)row * (DDIM / 4);
    #pragma unroll
    for (int i = 0; i < 8; i++) {
        dx[lane + 32 * i] = pack_e4m3x4(xv[i].x * sx, xv[i].y * sx, xv[i].z * sx, xv[i].w * sx);
        dy[lane + 32 * i] = pack_e4m3x4(yv[i].x * sy, yv[i].y * sy, yv[i].z * sy, yv[i].w * sy);
    }
}

// ---------------------------------------------------------------------------
// Kernel 2: fp8 mma.sync GEMM with f16 accumulation, 128x128 tile, 2 CTAs/SM,
// fused hinge epilogue + deterministic last-CTA final reduction.
// 8 warps in 2(m) x 4(n); warp tile 64x32 => acc[4][4][2] (f16x2).
// ---------------------------------------------------------------------------
__global__ void __launch_bounds__(256, 2) gemm_hinge_kernel(float* __restrict__ out) {
    extern __shared__ char smem[];
    const uint32_t sb = smem_u32(smem);
    const int tid  = threadIdx.x;
    const int wid  = tid >> 5;
    const int lane = tid & 31;
    const int warp_m = wid & 1;
    const int warp_n = wid >> 1;
    const int bm = blockIdx.y * TILE_M;
    const int bn = blockIdx.x * TILE_N;

    uint32_t acc[4][4][2];
    #pragma unroll
    for (int i = 0; i < 4; i++)
        #pragma unroll
        for (int j = 0; j < 4; j++) { acc[i][j][0] = 0u; acc[i][j][1] = 0u; }

    // loaders: 128-B rows of fp8; each chunk is 128 fp8 columns
    const int ld_row = tid >> 3;          // 0..31
    const int ld_c   = tid & 7;           // 16-B column
    auto load_chunk = [&](int j, int s) {
        const uint32_t stage = sb + s * STAGE_BYTES;
        const int k0w = j * (KC / 4);     // u32-word offset of chunk
        #pragma unroll
        for (int q = 0; q < 4; q++) {     // A: 128 rows
            int row = ld_row + q * 32;
            const uint32_t* src = g_X8 + (size_t)(bm + row) * (DDIM / 4) + k0w + ld_c * 4;
            uint32_t off = (uint32_t)(row * 128 + ld_c * 16);
            CP_ASYNC_16(stage + SW128(off), src);
        }
        #pragma unroll
        for (int q = 0; q < 4; q++) {     // B: 128 rows
            int row = ld_row + q * 32;
            const uint32_t* src = g_Y8 + (size_t)(bn + row) * (DDIM / 4) + k0w + ld_c * 4;
            uint32_t off = (uint32_t)(row * 128 + ld_c * 16);
            CP_ASYNC_16(stage + A_BYTES + SW128(off), src);
        }
    };

    #pragma unroll
    for (int j = 0; j < STAGES - 1; j++) {
        load_chunk(j, j);
        CP_ASYNC_COMMIT();
    }

    // ldmatrix per-lane components (kstep = 32 bytes)
    const int a_row_l = (lane & 15);
    const int a_kb_l  = (lane >> 4) << 4;
    const int b_row_l = (lane & 7) + ((lane >> 4) << 3);
    const int b_kb_l  = ((lane >> 3) & 1) << 4;

    int s = 0;
    for (int j = 0; j < NCHUNK; j++) {
        CP_ASYNC_WAIT_1();
        __syncthreads();
        if (j + STAGES - 1 < NCHUNK) {
            int s2 = s + STAGES - 1; if (s2 >= STAGES) s2 -= STAGES;
            load_chunk(j + STAGES - 1, s2);
        }
        CP_ASYNC_COMMIT();

        const uint32_t Abase = sb + s * STAGE_BYTES;
        const uint32_t Bbase = Abase + A_BYTES;

        #pragma unroll
        for (int kk = 0; kk < 4; kk++) {          // 4 ksteps x 32 fp8 = 128
            const int kb = kk * 32;
            uint32_t afr[4][4];
            #pragma unroll
            for (int im = 0; im < 4; im++) {
                int row = warp_m * 64 + im * 16 + a_row_l;
                ldsm_x4(afr[im], Abase + SW128((uint32_t)(row * 128 + kb + a_kb_l)));
            }
            uint32_t bfr[2][4];
            #pragma unroll
            for (int jb = 0; jb < 2; jb++) {
                int row = warp_n * 32 + jb * 16 + b_row_l;
                ldsm_x4(bfr[jb], Bbase + SW128((uint32_t)(row * 128 + kb + b_kb_l)));
            }
            #pragma unroll
            for (int im = 0; im < 4; im++) {
                #pragma unroll
                for (int jb = 0; jb < 2; jb++) {
                    mma_fp8_h(acc[im][2 * jb],     afr[im], &bfr[jb][0]);
                    mma_fp8_h(acc[im][2 * jb + 1], afr[im], &bfr[jb][2]);
                }
            }
        }
        s++; if (s >= STAGES) s = 0;
    }

    // Fused epilogue: acc holds 256*S in f16x2. hinge = max(0,(D-pos)+acc/256)
    float psum = 0.f;
    #pragma unroll
    for (int im = 0; im < 4; im++) {
        const int r0 = bm + warp_m * 64 + im * 16 + (lane >> 2);
        const int r1 = r0 + 8;
        const float d0 = DELTA - __ldg(&g_pos[r0]);
        const float d1 = DELTA - __ldg(&g_pos[r1]);
        #pragma unroll
        for (int t = 0; t < 4; t++) {
            const int c0 = bn + warp_n * 32 + t * 8 + (lane & 3) * 2;
            const int c1 = c0 + 1;
            float2 v0 = __half22float2(*reinterpret_cast<__half2*>(&acc[im][t][0])); // row r0
            float2 v1 = __half22float2(*reinterpret_cast<__half2*>(&acc[im][t][1])); // row r1
            float h;
            h = fmaxf(0.f, fmaf(v0.x, INV_SS, d0)); psum += (r0 != c0) ? h : 0.f;
            h = fmaxf(0.f, fmaf(v0.y, INV_SS, d0)); psum += (r0 != c1) ? h : 0.f;
            h = fmaxf(0.f, fmaf(v1.x, INV_SS, d1)); psum += (r1 != c0) ? h : 0.f;
            h = fmaxf(0.f, fmaf(v1.y, INV_SS, d1)); psum += (r1 != c1) ? h : 0.f;
        }
    }

    #pragma unroll
    for (int off = 16; off > 0; off >>= 1)
        psum += __shfl_down_sync(0xFFFFFFFFu, psum, off);
    __shared__ float warp_sums[8];
    __shared__ bool s_last;
    if (lane == 0) warp_sums[wid] = psum;
    __syncthreads();
    if (tid == 0) {
        float tot = 0.f;
        #pragma unroll
        for (int w = 0; w < 8; w++) tot += warp_sums[w];
        g_partials[blockIdx.y * GRID_N + blockIdx.x] = tot;
        __threadfence();
        unsigned t = atomicAdd(&g_ticket, 1u);
        s_last = (t == NUM_TILES - 1);
    }
    __syncthreads();

    if (s_last) {
        float sloc = 0.f;
        #pragma unroll
        for (int i = 0; i < NUM_TILES / 256; i++)
            sloc += __ldcg(&g_partials[tid + i * 256]);
        #pragma unroll
        for (int off = 16; off > 0; off >>= 1)
            sloc += __shfl_down_sync(0xFFFFFFFFu, sloc, off);
        if (lane == 0) warp_sums[wid] = sloc;
        __syncthreads();
        if (tid == 0) {
            float tot = 0.f;
            #pragma unroll
            for (int w = 0; w < 8; w++) tot += warp_sums[w];
            out[0] = tot;
            g_ticket = 0;   // reset for next graph replay
        }
    }
}

extern "C" void kernel_launch(void* const* d_in, const int* in_sizes, int n_in,
                              void* d_out, int out_size) {
    const float* X = (const float*)d_in[0];
    const float* Y = (const float*)d_in[1];
    float* out = (float*)d_out;

    cudaFuncSetAttribute(gemm_hinge_kernel,
                         cudaFuncAttributeMaxDynamicSharedMemorySize, SMEM_TOTAL);

    normalize_kernel<<<NROWS / 8, 256>>>(X, Y);
    dim3 grid(GRID_N, GRID_M);
    gemm_hinge_kernel<<<grid, 256, SMEM_TOTAL>>>(out);
}